// round 13
// baseline (speedup 1.0000x reference)
#include <cuda_runtime.h>
#include <cstddef>

// B=2, N=4096, K=48, Q=20
// inputs : d_in[0]=S (i32), d_in[1]=h (f32), d_in[2]=J (f32), d_in[3]=edge_idx (i32)
// output : d_out = [ U (B) | U_i (B*N*Q) ] fp32
//
// Best-measured design: dense (group,q) LDG gather (one thread per output
// element, 48-deep unroll, 4 accumulators, __ldcs streaming loads), fused
// last-block U reduction. This round fixes per-SM work balance only:
// grid 1024 x 160 (6.92 blk/SM, 8% imbalance) vs 512 x 320 (3.46, 15%).

namespace {
constexpr int Bc = 2;
constexpr int Nc = 4096;
constexpr int Kc = 48;
constexpr int Qc = 20;
constexpr int GPB = 8;                  // groups per block
constexpr int TPB = GPB * Qc;           // 160 threads = 5 full warps
constexpr int GROUPS = Bc * Nc;         // 8192
constexpr int NBLK = GROUPS / GPB;      // 1024
constexpr int BLK_PER_B = NBLK / Bc;    // 512
}

__device__ float g_partial[NBLK];
__device__ int   g_count = 0;           // self-resetting epoch counter

__global__ __launch_bounds__(TPB)
void potts_fused_kernel(const int* __restrict__ S,
                        const float* __restrict__ h,
                        const float* __restrict__ J,
                        const int* __restrict__ eidx,
                        float* __restrict__ out)
{
    const int tid   = threadIdx.x;
    const int gl    = tid / Qc;                 // 0..7
    const int q     = tid - gl * Qc;            // 0..19
    const int group = blockIdx.x * GPB + gl;

    __shared__ int   s_sh[GPB][Kc];
    __shared__ float c_sh[GPB];
    __shared__ float red[TPB];
    __shared__ bool  is_last;

    // Gather this block's 8*48 neighbor states (S: 32 KB, L2-resident).
    const int ebase = blockIdx.x * GPB * Kc;
    #pragma unroll
    for (int t = tid; t < GPB * Kc; t += TPB) {
        const int g_of = t / Kc;
        const int k_of = t - g_of * Kc;
        const int grp  = blockIdx.x * GPB + g_of;
        const int b_of = grp >> 12;
        s_sh[g_of][k_of] = S[b_of * Nc + eidx[ebase + t]];
    }
    __syncthreads();

    // Row pointer for this q: J[group][k][q][*], stride Q*Q floats per k.
    const float* Jg   = J + (size_t)group * (Kc * Qc * Qc) + (size_t)q * Qc;
    const int*   srow = s_sh[gl];

    float a0 = 0.f, a1 = 0.f, a2 = 0.f, a3 = 0.f;
    #pragma unroll
    for (int k = 0; k < Kc; k += 4) {
        a0 += __ldcs(Jg + (size_t)(k + 0) * (Qc * Qc) + srow[k + 0]);
        a1 += __ldcs(Jg + (size_t)(k + 1) * (Qc * Qc) + srow[k + 1]);
        a2 += __ldcs(Jg + (size_t)(k + 2) * (Qc * Qc) + srow[k + 2]);
        a3 += __ldcs(Jg + (size_t)(k + 3) * (Qc * Qc) + srow[k + 3]);
    }
    const float ji = (a0 + a1) + (a2 + a3);
    const float hv = h[(size_t)group * Qc + q];
    const float ui = hv + ji;
    out[Bc + (size_t)group * Qc + q] = ui;

    // Per-group U contribution: 0.5*(U_i[s]+h[s]) at s = S[group].
    if (q == S[group]) {
        c_sh[gl] = 0.5f * (ui + hv);
    }
    __syncthreads();

    // Per-block partial + epoch counter (threadFenceReduction pattern).
    if (tid == 0) {
        float s = 0.f;
        #pragma unroll
        for (int g = 0; g < GPB; g++) s += c_sh[g];
        g_partial[blockIdx.x] = s;
        __threadfence();
        is_last = (atomicAdd(&g_count, 1) == NBLK - 1);
    }
    __syncthreads();

    if (is_last) {
        // Deterministic reduction of the 512 partials per batch.
        #pragma unroll
        for (int b = 0; b < Bc; b++) {
            float s = 0.f;
            for (int i = tid; i < BLK_PER_B; i += TPB)
                s += g_partial[b * BLK_PER_B + i];
            red[tid] = s;
            __syncthreads();
            if (tid == 0) {
                float t = 0.f;
                #pragma unroll
                for (int i = 0; i < TPB; i++) t += red[i];
                out[b] = t;
            }
            __syncthreads();
        }
        if (tid == 0) g_count = 0;   // reset for next graph replay
    }
}

extern "C" void kernel_launch(void* const* d_in, const int* in_sizes, int n_in,
                              void* d_out, int out_size)
{
    const int*   S    = (const int*)  d_in[0];
    const float* h    = (const float*)d_in[1];
    const float* J    = (const float*)d_in[2];
    const int*   eidx = (const int*)  d_in[3];
    float*       out  = (float*)      d_out;

    potts_fused_kernel<<<NBLK, TPB>>>(S, h, J, eidx, out);

    (void)in_sizes; (void)n_in; (void)out_size;
}